// round 14
// baseline (speedup 1.0000x reference)
#include <cuda_runtime.h>
#include <cstdint>

// ---------------- problem constants ----------------
constexpr int B_    = 16;
constexpr int CIN   = 64;
constexpr int Hh    = 66;
constexpr int Ww    = 66;
constexpr int COUT  = 128;
constexpr int HOUT  = 64;
constexpr int WOUT  = 64;

constexpr int NPIX_IN  = Hh * Ww;      // 4356
constexpr int NPIX_OUT = HOUT * WOUT;  // 4096

constexpr size_t N_PRE  = (size_t)B_ * CIN  * NPIX_IN;   // 4,460,544
constexpr size_t N_POST = (size_t)B_ * COUT * NPIX_OUT;  // 8,388,608

constexpr int KHALF = B_ * NPIX_OUT;   // 65536
constexpr int KTOT  = 2 * KHALF;       // 131072 (stacked: slab0 = A-term, slab1 = -B-term)

constexpr int SPLITK = 32;
constexpr int KCHUNK = KTOT / SPLITK;  // 4096
constexpr int TK     = 16;
constexpr int NSTAGE = KCHUNK / TK;    // 256

constexpr size_t YSLAB = (size_t)KHALF * COUT;      // 8,388,608 floats per slab
constexpr size_t XSLAB = (size_t)B_ * NPIX_IN * CIN; // 4,460,544 floats per slab

// ---------------- scratch (device globals, no allocation) ----------------
__device__ float g_Yt[2 * YSLAB];                     // [2*K][COUT] pixel-major, 0.5/-0.5 folded in
__device__ float g_Xt[2 * XSLAB];                     // [2*B*66*66][CIN] pixel-major
__device__ float g_part[(size_t)9 * SPLITK * COUT * CIN]; // split-K partials

// ---------------- helpers ----------------
__device__ __forceinline__ void cp16(void* s, const void* g) {
    uint32_t sa = (uint32_t)__cvta_generic_to_shared(s);
    asm volatile("cp.async.cg.shared.global [%0], [%1], 16;" :: "r"(sa), "l"(g) : "memory");
}
__device__ __forceinline__ unsigned long long pack2(float lo, float hi) {
    unsigned long long r;
    asm("mov.b64 %0, {%1, %2};" : "=l"(r) : "f"(lo), "f"(hi));
    return r;
}
// Blackwell packed dual-fp32 FMA (FFMA2) — PTX-only, 2x fp32 throughput
__device__ __forceinline__ void fma2(unsigned long long& d, unsigned long long a, unsigned long long b) {
    asm("fma.rn.f32x2 %0, %1, %2, %0;" : "+l"(d) : "l"(a), "l"(b));
}

// ---------------- prep Y: tr_post out + transpose (B,COUT,64,64) -> [k][COUT] ----------------
__global__ void prep_y(const float* __restrict__ os, const float* __restrict__ tp,
                       float* __restrict__ trpost) {
    __shared__ float s0[32][33];
    __shared__ float s1[32][33];
    const int b  = blockIdx.z;
    const int ot = blockIdx.y * 32;   // cout tile
    const int pt = blockIdx.x * 32;   // pixel tile
    const int c  = threadIdx.x & 31;
    const int r0 = threadIdx.x >> 5;  // 0..7

#pragma unroll
    for (int r = 0; r < 4; r++) {
        int orow = r0 + r * 8;
        size_t idx = ((size_t)(b * COUT + ot + orow)) * NPIX_OUT + pt + c;
        float vo = os[idx];
        float vt = tp[idx];
        trpost[idx] = 0.5f * vt + vo;      // tr_post
        s0[orow][c] =  0.5f * vo;          // Y slab0 = +0.5*out_spike
        s1[orow][c] = -0.5f * vt;          // Y slab1 = -0.5*trace_post
    }
    __syncthreads();
#pragma unroll
    for (int r = 0; r < 4; r++) {
        int prow = r0 + r * 8;
        size_t k = (size_t)b * NPIX_OUT + pt + prow;
        g_Yt[k * COUT + ot + c]          = s0[c][prow];
        g_Yt[YSLAB + k * COUT + ot + c]  = s1[c][prow];
    }
}

// ---------------- prep X: tr_pre out + transpose (B,CIN,66,66) -> [pix][CIN] ----------------
__global__ void prep_x(const float* __restrict__ is, const float* __restrict__ trp,
                       float* __restrict__ trpre) {
    __shared__ float s0[32][33];
    __shared__ float s1[32][33];
    const int b  = blockIdx.z;
    const int it = blockIdx.y * 32;
    const int pt = blockIdx.x * 32;
    const int c  = threadIdx.x & 31;
    const int r0 = threadIdx.x >> 5;

#pragma unroll
    for (int r = 0; r < 4; r++) {
        int irow = r0 + r * 8;
        int pix = pt + c;
        if (pix < NPIX_IN) {
            size_t idx = ((size_t)(b * CIN + it + irow)) * NPIX_IN + pix;
            float vi = is[idx];
            float vt = trp[idx];
            trpre[idx] = 0.5f * vt + vi;   // tr_pre
            s0[irow][c] = vt;              // X slab0 = trace_pre (raw)
            s1[irow][c] = vi;              // X slab1 = in_spike
        }
    }
    __syncthreads();
#pragma unroll
    for (int r = 0; r < 4; r++) {
        int prow = r0 + r * 8;
        int pix = pt + prow;
        if (pix < NPIX_IN) {
            size_t row = (size_t)b * NPIX_IN + pix;
            g_Xt[row * CIN + it + c]         = s0[c][prow];
            g_Xt[XSLAB + row * CIN + it + c] = s1[c][prow];
        }
    }
}

// ---------------- GEMM: acc[o,i] per shift, split-K, FFMA2 inner loop ----------------
__global__ __launch_bounds__(128, 2) void stdp_gemm() {
    __shared__ float Ys[2][TK * COUT];
    __shared__ float Xs[2][TK * CIN];

    const int split = blockIdx.x;
    const int shift = blockIdx.y;
    const int hh = shift / 3, ww = shift % 3;
    const int tid = threadIdx.x;
    const int tm = tid & 15;   // 16 M-groups of 8 rows  -> 128
    const int tn = tid >> 4;   // 8 N-groups of 8 cols   -> 64
    const int k0 = split * KCHUNK;

    unsigned long long acc[8][4];
#pragma unroll
    for (int m = 0; m < 8; m++)
#pragma unroll
        for (int n = 0; n < 4; n++) acc[m][n] = 0ull;

    auto load_stage = [&](int stg, int buf) {
        const int kb = k0 + stg * TK;
        // Y tile: TK*128 floats = 512 x 16B
#pragma unroll
        for (int j = 0; j < 4; j++) {
            int flat = tid + j * 128;
            int kk = flat >> 5, o4 = flat & 31;
            cp16(&Ys[buf][kk * COUT + o4 * 4],
                 g_Yt + (size_t)(kb + kk) * COUT + o4 * 4);
        }
        // X tile: TK*64 floats = 256 x 16B (shifted window rows)
#pragma unroll
        for (int j = 0; j < 2; j++) {
            int flat = tid + j * 128;
            int kk = flat >> 4, i4 = flat & 15;
            int k = kb + kk;
            int s  = k >> 16;
            int r  = k & 65535;
            int b  = r >> 12;
            int pq = r & 4095;
            int p  = pq >> 6, q = pq & 63;
            size_t row = (size_t)((s * B_ + b) * NPIX_IN + (p + hh) * Ww + (q + ww));
            cp16(&Xs[buf][kk * CIN + i4 * 4], g_Xt + row * CIN + i4 * 4);
        }
        asm volatile("cp.async.commit_group;" ::: "memory");
    };

    load_stage(0, 0);
    load_stage(1, 1);

    for (int s = 0; s < NSTAGE; s++) {
        const int buf = s & 1;
        asm volatile("cp.async.wait_group 1;" ::: "memory");
        __syncthreads();
#pragma unroll
        for (int kk = 0; kk < TK; kk++) {
            const float4 ya = *(const float4*)&Ys[buf][kk * COUT + tm * 8];
            const float4 yb = *(const float4*)&Ys[buf][kk * COUT + tm * 8 + 4];
            const float4 xa = *(const float4*)&Xs[buf][kk * CIN + tn * 8];
            const float4 xb = *(const float4*)&Xs[buf][kk * CIN + tn * 8 + 4];
            unsigned long long xv[4] = { pack2(xa.x, xa.y), pack2(xa.z, xa.w),
                                         pack2(xb.x, xb.y), pack2(xb.z, xb.w) };
            float yv[8] = { ya.x, ya.y, ya.z, ya.w, yb.x, yb.y, yb.z, yb.w };
#pragma unroll
            for (int m = 0; m < 8; m++) {
                unsigned long long y2 = pack2(yv[m], yv[m]);
#pragma unroll
                for (int n = 0; n < 4; n++) fma2(acc[m][n], y2, xv[n]);
            }
        }
        __syncthreads();
        if (s + 2 < NSTAGE) load_stage(s + 2, buf);
        else asm volatile("cp.async.commit_group;" ::: "memory"); // keep group count in lockstep
    }

    // write deterministic split-K partial
    float* outp = g_part + ((size_t)shift * SPLITK + split) * (COUT * CIN);
#pragma unroll
    for (int m = 0; m < 8; m++) {
        int row = tm * 8 + m;
#pragma unroll
        for (int n = 0; n < 4; n++) {
            float2 v;
            asm("mov.b64 {%0, %1}, %2;" : "=f"(v.x), "=f"(v.y) : "l"(acc[m][n]));
            *(float2*)&outp[row * CIN + tn * 8 + n * 2] = v;
        }
    }
}

// ---------------- reduce split-K partials, apply weight ----------------
__global__ void stdp_reduce(const float* __restrict__ weight, float* __restrict__ dw) {
    const int shift = blockIdx.y;                         // h*3+w
    const int oi = blockIdx.x * 256 + threadIdx.x;        // o*64 + i  (0..8191)
    const float* p = g_part + (size_t)shift * SPLITK * (COUT * CIN) + oi;
    float sum = 0.f;
#pragma unroll
    for (int sp = 0; sp < SPLITK; sp++) sum += p[(size_t)sp * (COUT * CIN)];
    const int j = oi * 9 + shift;                         // (COUT,CIN,3,3) flat
    dw[j] = weight[j] * sum;
}

// ---------------- entry ----------------
extern "C" void kernel_launch(void* const* d_in, const int* in_sizes, int n_in,
                              void* d_out, int out_size) {
    const float* in_spike   = (const float*)d_in[0];
    const float* out_spike  = (const float*)d_in[1];
    const float* trace_pre  = (const float*)d_in[2];
    const float* trace_post = (const float*)d_in[3];
    const float* weight     = (const float*)d_in[4];
    float* out = (float*)d_out;

    // tr_post + Y transpose
    prep_y<<<dim3(NPIX_OUT / 32, COUT / 32, B_), 256>>>(out_spike, trace_post, out + N_PRE);
    // tr_pre + X transpose
    prep_x<<<dim3((NPIX_IN + 31) / 32, CIN / 32, B_), 256>>>(in_spike, trace_pre, out);
    // 9-shift stacked-K GEMM, split-K partials
    stdp_gemm<<<dim3(SPLITK, 9), 128>>>();
    // combine + weight
    stdp_reduce<<<dim3((COUT * CIN) / 256, 9), 256>>>(weight, out + N_PRE + N_POST);
    (void)in_sizes; (void)n_in; (void)out_size;
}

// round 15
// speedup vs baseline: 1.0019x; 1.0019x over previous
#include <cuda_runtime.h>
#include <cstdint>

// ---------------- problem constants ----------------
constexpr int B_    = 16;
constexpr int CIN   = 64;
constexpr int Hh    = 66;
constexpr int Ww    = 66;
constexpr int COUT  = 128;
constexpr int HOUT  = 64;
constexpr int WOUT  = 64;

constexpr int NPIX_IN  = Hh * Ww;      // 4356
constexpr int NPIX_OUT = HOUT * WOUT;  // 4096

constexpr size_t N_PRE  = (size_t)B_ * CIN  * NPIX_IN;   // 4,460,544
constexpr size_t N_POST = (size_t)B_ * COUT * NPIX_OUT;  // 8,388,608

constexpr int KHALF = B_ * NPIX_OUT;   // 65536
constexpr int KTOT  = 2 * KHALF;       // 131072 (stacked: slab0 = A-term, slab1 = -B-term)

constexpr int SPLITK = 32;
constexpr int KCHUNK = KTOT / SPLITK;  // 4096
constexpr int TK     = 16;
constexpr int NSTAGE = KCHUNK / TK;    // 256

constexpr size_t YSLAB = (size_t)KHALF * COUT;      // 8,388,608 floats per slab
constexpr size_t XSLAB = (size_t)B_ * NPIX_IN * CIN; // 4,460,544 floats per slab

// ---------------- scratch (device globals, no allocation) ----------------
__device__ float g_Yt[2 * YSLAB];                     // [2*K][COUT] pixel-major, 0.5/-0.5 folded in
__device__ float g_Xt[2 * XSLAB];                     // [2*B*66*66][CIN] pixel-major
__device__ float g_part[(size_t)9 * SPLITK * COUT * CIN]; // split-K partials

// ---------------- helpers ----------------
__device__ __forceinline__ void cp16(void* s, const void* g) {
    uint32_t sa = (uint32_t)__cvta_generic_to_shared(s);
    asm volatile("cp.async.cg.shared.global [%0], [%1], 16;" :: "r"(sa), "l"(g) : "memory");
}
__device__ __forceinline__ unsigned long long pack2(float lo, float hi) {
    unsigned long long r;
    asm("mov.b64 %0, {%1, %2};" : "=l"(r) : "f"(lo), "f"(hi));
    return r;
}
// Blackwell packed dual-fp32 FMA (FFMA2) — PTX-only, 2x fp32 throughput
__device__ __forceinline__ void fma2(unsigned long long& d, unsigned long long a, unsigned long long b) {
    asm("fma.rn.f32x2 %0, %1, %2, %0;" : "+l"(d) : "l"(a), "l"(b));
}

// ---------------- prep Y: tr_post out + transpose (B,COUT,64,64) -> [k][COUT] ----------------
__global__ void prep_y(const float* __restrict__ os, const float* __restrict__ tp,
                       float* __restrict__ trpost) {
    __shared__ float s0[32][33];
    __shared__ float s1[32][33];
    const int b  = blockIdx.z;
    const int ot = blockIdx.y * 32;   // cout tile
    const int pt = blockIdx.x * 32;   // pixel tile
    const int c  = threadIdx.x & 31;
    const int r0 = threadIdx.x >> 5;  // 0..7

#pragma unroll
    for (int r = 0; r < 4; r++) {
        int orow = r0 + r * 8;
        size_t idx = ((size_t)(b * COUT + ot + orow)) * NPIX_OUT + pt + c;
        float vo = os[idx];
        float vt = tp[idx];
        trpost[idx] = 0.5f * vt + vo;      // tr_post
        s0[orow][c] =  0.5f * vo;          // Y slab0 = +0.5*out_spike
        s1[orow][c] = -0.5f * vt;          // Y slab1 = -0.5*trace_post
    }
    __syncthreads();
#pragma unroll
    for (int r = 0; r < 4; r++) {
        int prow = r0 + r * 8;
        size_t k = (size_t)b * NPIX_OUT + pt + prow;
        g_Yt[k * COUT + ot + c]          = s0[c][prow];
        g_Yt[YSLAB + k * COUT + ot + c]  = s1[c][prow];
    }
}

// ---------------- prep X: tr_pre out + transpose (B,CIN,66,66) -> [pix][CIN] ----------------
__global__ void prep_x(const float* __restrict__ is, const float* __restrict__ trp,
                       float* __restrict__ trpre) {
    __shared__ float s0[32][33];
    __shared__ float s1[32][33];
    const int b  = blockIdx.z;
    const int it = blockIdx.y * 32;
    const int pt = blockIdx.x * 32;
    const int c  = threadIdx.x & 31;
    const int r0 = threadIdx.x >> 5;

#pragma unroll
    for (int r = 0; r < 4; r++) {
        int irow = r0 + r * 8;
        int pix = pt + c;
        if (pix < NPIX_IN) {
            size_t idx = ((size_t)(b * CIN + it + irow)) * NPIX_IN + pix;
            float vi = is[idx];
            float vt = trp[idx];
            trpre[idx] = 0.5f * vt + vi;   // tr_pre
            s0[irow][c] = vt;              // X slab0 = trace_pre (raw)
            s1[irow][c] = vi;              // X slab1 = in_spike
        }
    }
    __syncthreads();
#pragma unroll
    for (int r = 0; r < 4; r++) {
        int prow = r0 + r * 8;
        int pix = pt + prow;
        if (pix < NPIX_IN) {
            size_t row = (size_t)b * NPIX_IN + pix;
            g_Xt[row * CIN + it + c]         = s0[c][prow];
            g_Xt[XSLAB + row * CIN + it + c] = s1[c][prow];
        }
    }
}

// ---------------- GEMM: acc[o,i] per shift, split-K, FFMA2 inner loop ----------------
__global__ __launch_bounds__(128, 2) void stdp_gemm() {
    __shared__ float Ys[2][TK * COUT];
    __shared__ float Xs[2][TK * CIN];

    const int split = blockIdx.x;
    const int shift = blockIdx.y;
    const int hh = shift / 3, ww = shift % 3;
    const int tid = threadIdx.x;
    const int tm = tid & 15;   // 16 M-groups of 8 rows  -> 128
    const int tn = tid >> 4;   // 8 N-groups of 8 cols   -> 64
    const int k0 = split * KCHUNK;

    unsigned long long acc[8][4];
#pragma unroll
    for (int m = 0; m < 8; m++)
#pragma unroll
        for (int n = 0; n < 4; n++) acc[m][n] = 0ull;

    auto load_stage = [&](int stg, int buf) {
        const int kb = k0 + stg * TK;
        // Y tile: TK*128 floats = 512 x 16B
#pragma unroll
        for (int j = 0; j < 4; j++) {
            int flat = tid + j * 128;
            int kk = flat >> 5, o4 = flat & 31;
            cp16(&Ys[buf][kk * COUT + o4 * 4],
                 g_Yt + (size_t)(kb + kk) * COUT + o4 * 4);
        }
        // X tile: TK*64 floats = 256 x 16B (shifted window rows)
#pragma unroll
        for (int j = 0; j < 2; j++) {
            int flat = tid + j * 128;
            int kk = flat >> 4, i4 = flat & 15;
            int k = kb + kk;
            int s  = k >> 16;
            int r  = k & 65535;
            int b  = r >> 12;
            int pq = r & 4095;
            int p  = pq >> 6, q = pq & 63;
            size_t row = (size_t)((s * B_ + b) * NPIX_IN + (p + hh) * Ww + (q + ww));
            cp16(&Xs[buf][kk * CIN + i4 * 4], g_Xt + row * CIN + i4 * 4);
        }
        asm volatile("cp.async.commit_group;" ::: "memory");
    };

    load_stage(0, 0);
    load_stage(1, 1);

    for (int s = 0; s < NSTAGE; s++) {
        const int buf = s & 1;
        asm volatile("cp.async.wait_group 1;" ::: "memory");
        __syncthreads();
#pragma unroll
        for (int kk = 0; kk < TK; kk++) {
            const float4 ya = *(const float4*)&Ys[buf][kk * COUT + tm * 8];
            const float4 yb = *(const float4*)&Ys[buf][kk * COUT + tm * 8 + 4];
            const float4 xa = *(const float4*)&Xs[buf][kk * CIN + tn * 8];
            const float4 xb = *(const float4*)&Xs[buf][kk * CIN + tn * 8 + 4];
            unsigned long long xv[4] = { pack2(xa.x, xa.y), pack2(xa.z, xa.w),
                                         pack2(xb.x, xb.y), pack2(xb.z, xb.w) };
            float yv[8] = { ya.x, ya.y, ya.z, ya.w, yb.x, yb.y, yb.z, yb.w };
#pragma unroll
            for (int m = 0; m < 8; m++) {
                unsigned long long y2 = pack2(yv[m], yv[m]);
#pragma unroll
                for (int n = 0; n < 4; n++) fma2(acc[m][n], y2, xv[n]);
            }
        }
        __syncthreads();
        if (s + 2 < NSTAGE) load_stage(s + 2, buf);
        else asm volatile("cp.async.commit_group;" ::: "memory"); // keep group count in lockstep
    }

    // write deterministic split-K partial
    float* outp = g_part + ((size_t)shift * SPLITK + split) * (COUT * CIN);
#pragma unroll
    for (int m = 0; m < 8; m++) {
        int row = tm * 8 + m;
#pragma unroll
        for (int n = 0; n < 4; n++) {
            float2 v;
            asm("mov.b64 {%0, %1}, %2;" : "=f"(v.x), "=f"(v.y) : "l"(acc[m][n]));
            *(float2*)&outp[row * CIN + tn * 8 + n * 2] = v;
        }
    }
}

// ---------------- reduce split-K partials, apply weight ----------------
__global__ void stdp_reduce(const float* __restrict__ weight, float* __restrict__ dw) {
    const int shift = blockIdx.y;                         // h*3+w
    const int oi = blockIdx.x * 256 + threadIdx.x;        // o*64 + i  (0..8191)
    const float* p = g_part + (size_t)shift * SPLITK * (COUT * CIN) + oi;
    float sum = 0.f;
#pragma unroll
    for (int sp = 0; sp < SPLITK; sp++) sum += p[(size_t)sp * (COUT * CIN)];
    const int j = oi * 9 + shift;                         // (COUT,CIN,3,3) flat
    dw[j] = weight[j] * sum;
}

// ---------------- entry ----------------
extern "C" void kernel_launch(void* const* d_in, const int* in_sizes, int n_in,
                              void* d_out, int out_size) {
    const float* in_spike   = (const float*)d_in[0];
    const float* out_spike  = (const float*)d_in[1];
    const float* trace_pre  = (const float*)d_in[2];
    const float* trace_post = (const float*)d_in[3];
    const float* weight     = (const float*)d_in[4];
    float* out = (float*)d_out;

    // tr_post + Y transpose
    prep_y<<<dim3(NPIX_OUT / 32, COUT / 32, B_), 256>>>(out_spike, trace_post, out + N_PRE);
    // tr_pre + X transpose
    prep_x<<<dim3((NPIX_IN + 31) / 32, CIN / 32, B_), 256>>>(in_spike, trace_pre, out);
    // 9-shift stacked-K GEMM, split-K partials
    stdp_gemm<<<dim3(SPLITK, 9), 128>>>();
    // combine + weight
    stdp_reduce<<<dim3((COUT * CIN) / 256, 9), 256>>>(weight, out + N_PRE + N_POST);
    (void)in_sizes; (void)n_in; (void)out_size;
}